// round 14
// baseline (speedup 1.0000x reference)
#include <cuda_runtime.h>
#include <cuda.h>
#include <math.h>
#include <stdint.h>

#define T_FRAMES 16384
#define C        7
#define F_DIM    2048
#define LEN_Q    30
#define N_HEADS  4
#define D_FF     64

#define FPB      128                   // frames per block (GEMM M)
#define KC       32                    // K floats per TMA chunk (128 B rows)
#define CHUNKS   (F_DIM / KC)          // 64
#define NBUF     4                     // A-ring depth
#define CH_F     (FPB * KC)            // 4096 floats per A chunk (16 KB)
#define CH_BYTES (CH_F * 4)
#define ROWS     (FPB + LEN_Q - 1)     // 157
#define NSTR     33
#define NP_F     (ROWS * NSTR)         // 5181

#define THREADS  288                   // 8 compute warps + 1 producer warp
#define CWARPS   8

#define RING_F   (NBUF * CH_F)         // 16384 floats (64 KB)
#define B_F      (F_DIM * 8)           // 16384 floats (64 KB) : B[k][n], n padded to 8
#define DYN_BYTES ((RING_F + B_F) * 4 + 1024)

#define SW128(off) ((off) ^ (((off) >> 3) & 0x70))

__device__ __forceinline__ uint32_t smem_u32(const void* p) {
    uint32_t a;
    asm("{ .reg .u64 t; cvta.to.shared.u64 t, %1; cvt.u32.u64 %0, t; }"
        : "=r"(a) : "l"(p));
    return a;
}
__device__ __forceinline__ void mbar_init(uint32_t mbar, uint32_t cnt) {
    asm volatile("mbarrier.init.shared.b64 [%0], %1;" :: "r"(mbar), "r"(cnt) : "memory");
}
__device__ __forceinline__ void mbar_arrive(uint32_t mbar) {
    asm volatile("mbarrier.arrive.release.cta.shared::cta.b64 _, [%0];"
                 :: "r"(mbar) : "memory");
}
__device__ __forceinline__ void mbar_expect_tx(uint32_t mbar, uint32_t bytes) {
    asm volatile("mbarrier.arrive.expect_tx.shared.b64 _, [%0], %1;"
                 :: "r"(mbar), "r"(bytes) : "memory");
}
__device__ __forceinline__ void mbar_wait_parity(uint32_t mbar, uint32_t ph) {
    asm volatile(
        "{\n\t.reg .pred P;\n\t"
        "WAIT_%=:\n\t"
        "mbarrier.try_wait.parity.acquire.cta.shared::cta.b64 P, [%0], %1, 0x989680;\n\t"
        "@P bra.uni DONE_%=;\n\t"
        "bra.uni WAIT_%=;\n\t"
        "DONE_%=:\n\t}"
        :: "r"(mbar), "r"(ph) : "memory");
}
__device__ __forceinline__ void tma_2d(uint32_t dst, const void* tmap,
                                       int cx, int cy, uint32_t mbar) {
    asm volatile(
        "cp.async.bulk.tensor.2d.shared::cta.global.tile.mbarrier::complete_tx::bytes "
        "[%0], [%1, {%2, %3}], [%4];"
        :: "r"(dst), "l"(tmap), "r"(cx), "r"(cy), "r"(mbar) : "memory");
}
__device__ __forceinline__ uint32_t to_tf32(float f) {
    uint32_t r;
    asm("cvt.rna.tf32.f32 %0, %1;" : "=r"(r) : "f"(f));
    return r;
}
__device__ __forceinline__ void mma_tf32(float& c0, float& c1, float& c2, float& c3,
                                         uint32_t a0, uint32_t a1, uint32_t a2,
                                         uint32_t a3, uint32_t b0, uint32_t b1) {
    asm volatile(
        "mma.sync.aligned.m16n8k8.row.col.f32.tf32.tf32.f32 "
        "{%0,%1,%2,%3}, {%4,%5,%6,%7}, {%8,%9}, {%0,%1,%2,%3};"
        : "+f"(c0), "+f"(c1), "+f"(c2), "+f"(c3)
        : "r"(a0), "r"(a1), "r"(a2), "r"(a3), "r"(b0), "r"(b1));
}

extern __shared__ float dyn_raw[];

__global__ __launch_bounds__(THREADS, 1) void fused_kernel(
    const __grid_constant__ CUtensorMap tmapA,
    const float* __restrict__ x,    const float* __restrict__ Wfc,
    const float* __restrict__ Wq,   const float* __restrict__ Wk,
    const float* __restrict__ Wv,   const float* __restrict__ Wo,
    const float* __restrict__ ln1g, const float* __restrict__ ln1b,
    const float* __restrict__ Wff1, const float* __restrict__ Wff2,
    const float* __restrict__ ln2g, const float* __restrict__ ln2b,
    float* __restrict__ out)
{
    __shared__ float s_feats[ROWS][8];
    __shared__ float s_feas[FPB][8];
    __shared__ float sA[N_HEADS][C][8];
    __shared__ float sB[N_HEADS][C][8];
    __shared__ float sF1[D_FF * 9];
    __shared__ float sF2[C * 65];
    __shared__ __align__(8) unsigned long long m_fill[NBUF];
    __shared__ __align__(8) unsigned long long m_cons[NBUF];

    // 1024-align dynamic region (SW128 TMA tiles require it)
    uintptr_t praw = (uintptr_t)dyn_raw;
    float* ring = (float*)((praw + 1023) & ~(uintptr_t)1023);
    float* Bsm  = ring + RING_F;       // B[k][n] : 2048 x 8 (tf32-rounded)
    // tail aliases (ring dead after the GEMM)
    float* sN = ring;
    float* sP = ring + NP_F;

    const int tid  = threadIdx.x;
    const int lane = tid & 31;
    const int wid  = tid >> 5;
    const int t0   = blockIdx.x * FPB;

    if (tid < NBUF) {
        mbar_init(smem_u32(&m_fill[tid]), 1);
        mbar_init(smem_u32(&m_cons[tid]), CWARPS);
    }

    // ---- staging (all 288 threads) ----
    for (int i = tid; i < ROWS * C; i += THREADS) {
        const int r = i / C, c = i - r * C;
        const int g = t0 - (LEN_Q - 1) + r;
        s_feats[r][c] = (g >= 0) ? x[c * T_FRAMES + g] : 0.f;
    }
    for (int i = tid; i < D_FF * C; i += THREADS) {
        const int j = i / C, c = i - j * C;
        sF1[j * 9 + c] = Wff1[i];
    }
    for (int i = tid; i < C * D_FF; i += THREADS) {
        const int c = i / D_FF, j = i - c * D_FF;
        sF2[c * 65 + j] = Wff2[i];
    }
    // B[k][n] = tf32(Wfc[n][k]); n=7 zero-padded
    for (int i = tid; i < B_F; i += THREADS) {
        const int k = i >> 3, n = i & 7;
        const float v = (n < C) ? Wfc[n * F_DIM + k] : 0.f;
        Bsm[i] = __uint_as_float(to_tf32(v));
    }
    // per-head 7x7 contractions A_h = Wq^T Wk, B_h = Wo Wv
    if (tid < N_HEADS * C * C) {
        const int h = tid / (C * C);
        const int rem = tid - h * (C * C);
        const int c = rem / C, c2 = rem - c * C;
        const float* wq = Wq + (h * 64) * C + c;
        const float* wk = Wk + (h * 64) * C + c2;
        const float* wo = Wo + c * (N_HEADS * 64) + h * 64;
        const float* wv = Wv + (h * 64) * C + c2;
        float sa = 0.f, sb = 0.f;
#pragma unroll 8
        for (int d = 0; d < 64; ++d) {
            sa = fmaf(wq[d * C], wk[d * C], sa);
            sb = fmaf(wo[d],     wv[d * C], sb);
        }
        sA[h][c][c2] = sa;
        sB[h][c][c2] = sb;
    }
    __syncthreads();                 // mbars + staging visible

    const uint32_t ring_u32 = smem_u32(ring);

    if (wid == CWARPS) {
        // ================= producer warp =================
        if (lane == 0) {
            for (int g = 0; g < CHUNKS; ++g) {
                const int b = g & (NBUF - 1);
                if (g >= NBUF)
                    mbar_wait_parity(smem_u32(&m_cons[b]), ((g >> 2) + 1) & 1);
                mbar_expect_tx(smem_u32(&m_fill[b]), CH_BYTES);
                tma_2d(ring_u32 + b * CH_BYTES, &tmapA, g * KC, t0,
                       smem_u32(&m_fill[b]));
            }
        }
    } else {
        // ================= compute warps: tf32 MMA =================
        // warp w owns frames [w*16, w*16+16); m16n8k8 fragments.
        const int gq = lane >> 2;          // groupID (row within m16)
        const int tq = lane & 3;           // threadID_in_group
        const int f0 = wid * 16 + gq;      // A rows f0, f0+8 (within chunk)
        const uint32_t xm = (uint32_t)((f0 & 7) << 4);   // SW128 mask (same for f0+8)
        const char* rb0 = (const char*)ring + f0 * 128;
        const char* rb1 = rb0 + 8 * 128;

        float c0 = 0.f, c1 = 0.f, c2 = 0.f, c3 = 0.f;

        for (int g = 0; g < CHUNKS; ++g) {
            const int b = g & (NBUF - 1);
            mbar_wait_parity(smem_u32(&m_fill[b]), (g >> 2) & 1);
            const uint32_t cb = b * CH_BYTES;
            const float* bk = Bsm + (size_t)g * KC * 8 + gq;   // B[k][n=gq]

#pragma unroll
            for (int ks = 0; ks < 4; ++ks) {
                const uint32_t k0 = (uint32_t)(ks * 32 + tq * 4);
                const uint32_t o0 = cb + (k0 ^ xm);
                const uint32_t o1 = cb + ((k0 + 16) ^ xm);
                const uint32_t a0 = to_tf32(*(const float*)(rb0 + o0));
                const uint32_t a1 = to_tf32(*(const float*)(rb1 + o0));
                const uint32_t a2 = to_tf32(*(const float*)(rb0 + o1));
                const uint32_t a3 = to_tf32(*(const float*)(rb1 + o1));
                const uint32_t b0 = __float_as_uint(bk[(ks * 8 + tq) * 8]);
                const uint32_t b1 = __float_as_uint(bk[(ks * 8 + tq + 4) * 8]);
                mma_tf32(c0, c1, c2, c3, a0, a1, a2, a3, b0, b1);
            }
            if (lane == 0) mbar_arrive(smem_u32(&m_cons[b]));
        }

        // epilogue: d-frags -> tanh -> s_feas
        const int fr0 = wid * 16 + gq;
        const int cc  = tq * 2;
        s_feas[fr0][cc] = tanhf(c0);
        if (cc + 1 < C) s_feas[fr0][cc + 1] = tanhf(c1);
        s_feas[fr0 + 8][cc] = tanhf(c2);
        if (cc + 1 < C) s_feas[fr0 + 8][cc + 1] = tanhf(c3);
    }
    __syncthreads();                 // GEMM + s_feas done; ring dead

    // ---- N[r,h,c] = (A_h feat_r)[c],  P[r,h,c] = (B_h feat_r)[c] ----
    for (int i = tid; i < ROWS * N_HEADS * C; i += THREADS) {
        const int r = i / (N_HEADS * C);
        const int j = i - r * (N_HEADS * C);
        const int h = j / C, c = j - h * C;
        float sn = 0.f, sp = 0.f;
#pragma unroll
        for (int c2 = 0; c2 < C; ++c2) {
            const float fv = s_feats[r][c2];
            sn = fmaf(sA[h][c][c2], fv, sn);
            sp = fmaf(sB[h][c][c2], fv, sp);
        }
        sN[r * NSTR + h * 8 + c] = sn;
        sP[r * NSTR + h * 8 + c] = sp;
    }
    __syncthreads();

    // ---- attention (online softmax) + LN1 + FFN + LN2 ----
    for (int idx = tid; idx < FPB * N_HEADS; idx += THREADS) {
        const int f = idx >> 2;
        const int h = idx & 3;
        const int t = t0 + f;

        float ff[C];
#pragma unroll
        for (int c = 0; c < C; ++c) ff[c] = s_feas[f][c];

        const float* nb = sN + f * NSTR + h * 8;
        const float* pb = sP + f * NSTR + h * 8;

        float m = -1e30f, den = 0.f;
        float o[C];
#pragma unroll
        for (int c = 0; c < C; ++c) o[c] = 0.f;

#pragma unroll
        for (int l = 0; l < LEN_Q; ++l) {
            const float* nr = nb + l * NSTR;
            float s = ff[0] * nr[0];
#pragma unroll
            for (int c = 1; c < C; ++c) s = fmaf(ff[c], nr[c], s);
            s *= 0.125f;
            const float mn = fmaxf(m, s);
            const float corr = __expf(m - mn);
            const float wgt = __expf(s - mn);
            den = den * corr + wgt;
            const float* pr = pb + l * NSTR;
#pragma unroll
            for (int c = 0; c < C; ++c)
                o[c] = fmaf(o[c], corr, wgt * pr[c]);
            m = mn;
        }
        const float inv = 1.f / den;
#pragma unroll
        for (int c = 0; c < C; ++c) o[c] *= inv;

#pragma unroll
        for (int c = 0; c < C; ++c) {
            o[c] += __shfl_xor_sync(0xffffffffu, o[c], 1);
            o[c] += __shfl_xor_sync(0xffffffffu, o[c], 2);
        }

        float res[C];
        float mu = 0.f;
#pragma unroll
        for (int c = 0; c < C; ++c) { res[c] = o[c] + ff[c]; mu += res[c]; }
        mu *= (1.f / C);
        float var = 0.f;
#pragma unroll
        for (int c = 0; c < C; ++c) { const float dv = res[c] - mu; var += dv * dv; }
        var *= (1.f / C);
        float rs = rsqrtf(var + 1e-5f);
#pragma unroll
        for (int c = 0; c < C; ++c) res[c] = (res[c] - mu) * rs * ln1g[c] + ln1b[c];

        float y[C];
#pragma unroll
        for (int c = 0; c < C; ++c) y[c] = 0.f;
        const int j0 = h * 16;
#pragma unroll
        for (int jj = 0; jj < 16; ++jj) {
            const int j = j0 + jj;
            float a = 0.f;
#pragma unroll
            for (int c = 0; c < C; ++c) a = fmaf(res[c], sF1[j * 9 + c], a);
            a = fmaxf(a, 0.f);
#pragma unroll
            for (int c = 0; c < C; ++c) y[c] = fmaf(a, sF2[c * 65 + j], y[c]);
        }
#pragma unroll
        for (int c = 0; c < C; ++c) {
            y[c] += __shfl_xor_sync(0xffffffffu, y[c], 1);
            y[c] += __shfl_xor_sync(0xffffffffu, y[c], 2);
        }

        if (h == 0) {
            float z[C];
            mu = 0.f;
#pragma unroll
            for (int c = 0; c < C; ++c) { z[c] = y[c] + res[c]; mu += z[c]; }
            mu *= (1.f / C);
            var = 0.f;
#pragma unroll
            for (int c = 0; c < C; ++c) { const float dv = z[c] - mu; var += dv * dv; }
            var *= (1.f / C);
            rs = rsqrtf(var + 1e-5f);
#pragma unroll
            for (int c = 0; c < C; ++c)
                out[t * C + c] = (z[c] - mu) * rs * ln2g[c] + ln2b[c];
        }
    }
}

// ---------------------------------------------------------------------------
typedef CUresult (*EncodeFn)(
    CUtensorMap*, CUtensorMapDataType, cuuint32_t, void*,
    const cuuint64_t*, const cuuint64_t*, const cuuint32_t*, const cuuint32_t*,
    CUtensorMapInterleave, CUtensorMapSwizzle, CUtensorMapL2promotion,
    CUtensorMapFloatOOBfill);

extern "C" void kernel_launch(void* const* d_in, const int* in_sizes, int n_in,
                              void* d_out, int out_size) {
    const float* x    = (const float*)d_in[0];
    const float* LF   = (const float*)d_in[1];
    const float* Wfc  = (const float*)d_in[2];
    const float* Wq   = (const float*)d_in[3];
    const float* Wk   = (const float*)d_in[4];
    const float* Wv   = (const float*)d_in[5];
    const float* Wo   = (const float*)d_in[6];
    const float* ln1g = (const float*)d_in[7];
    const float* ln1b = (const float*)d_in[8];
    const float* Wff1 = (const float*)d_in[9];
    const float* Wff2 = (const float*)d_in[10];
    const float* ln2g = (const float*)d_in[11];
    const float* ln2b = (const float*)d_in[12];
    float* out = (float*)d_out;

    static EncodeFn enc = nullptr;
    if (!enc) {
        void* fp = nullptr;
        cudaDriverEntryPointQueryResult st;
        cudaGetDriverEntryPointByVersion("cuTensorMapEncodeTiled", &fp, 12000,
                                         cudaEnableDefault, &st);
        enc = (EncodeFn)fp;
    }

    CUtensorMap tmapA;
    cuuint64_t dims[2]    = {F_DIM, T_FRAMES};
    cuuint64_t strides[1] = {F_DIM * sizeof(float)};
    cuuint32_t box[2]     = {KC, FPB};
    cuuint32_t es[2]      = {1, 1};
    enc(&tmapA, CU_TENSOR_MAP_DATA_TYPE_FLOAT32, 2, (void*)LF,
        dims, strides, box, es,
        CU_TENSOR_MAP_INTERLEAVE_NONE, CU_TENSOR_MAP_SWIZZLE_128B,
        CU_TENSOR_MAP_L2_PROMOTION_L2_128B, CU_TENSOR_MAP_FLOAT_OOB_FILL_NONE);

    cudaFuncSetAttribute(fused_kernel,
                         cudaFuncAttributeMaxDynamicSharedMemorySize, DYN_BYTES);

    fused_kernel<<<T_FRAMES / FPB, THREADS, DYN_BYTES>>>(
        tmapA, x, LF ? Wfc : Wfc, Wq, Wk, Wv, Wo, ln1g, ln1b,
        Wff1, Wff2, ln2g, ln2b, out);
}